// round 1
// baseline (speedup 1.0000x reference)
#include <cuda_runtime.h>
#include <math.h>

#define BATCH 1024
#define NV    6890
#define NJ    24
#define NB    10
#define NP    207
#define KP    224          // 10 betas + 207 pose_feature + 1 (v_template) + 6 pad
#define NCOL  20670        // V*3
#define NPAD  20736        // padded N (162 * 128)

// ---------------- scratch (device globals; no allocation allowed) ----------------
__device__ float g_W[KP * NPAD];            // combined weight matrix  (18.6 MB)
__device__ float g_vposed[BATCH * NPAD];    // v_posed                 (84.9 MB)
__device__ float g_AB[BATCH * KP];          // per-batch GEMM A rows
__device__ float g_A[BATCH * NJ * 12];      // per-batch skinning transforms (3x4)
__device__ float g_root[BATCH * 3];         // posed joint 0 (root)
__device__ float g_Jt[NJ * 3];              // J_regressor @ v_template
__device__ float g_Jsd[NJ * 3 * NB];        // J_regressor @ shapedirs

__constant__ int c_parents[NJ] = {-1,0,0,0,1,2,3,4,5,6,7,8,9,9,9,12,13,14,16,17,18,19,20,21};

// output section offsets (floats)
#define OFF_VERTS 0
#define OFF_J     (BATCH * NCOL)                 // 21166080
#define OFF_R     (OFF_J + BATCH * NJ * 3)       // +73728
#define OFF_F     (OFF_R + BATCH * NJ * 9)       // +221184

// ============================================================================
// Kernel 1: factorized joint regressor:  g_Jt[j,k], g_Jsd[j,k,l]
// one block per joint, 256 threads
// ============================================================================
__global__ void k_jreg(const float* __restrict__ Jreg,
                       const float* __restrict__ vtmpl,
                       const float* __restrict__ shapedirs) {
    int j = blockIdx.x;
    int tid = threadIdx.x;
    float acc[33];
#pragma unroll
    for (int i = 0; i < 33; i++) acc[i] = 0.f;

    for (int v = tid; v < NV; v += 256) {
        float r = Jreg[j * NV + v];
#pragma unroll
        for (int k = 0; k < 3; k++) {
            acc[k] = fmaf(r, vtmpl[v * 3 + k], acc[k]);
#pragma unroll
            for (int l = 0; l < NB; l++)
                acc[3 + k * NB + l] = fmaf(r, shapedirs[(v * 3 + k) * NB + l], acc[3 + k * NB + l]);
        }
    }
    __shared__ float part[8][33];
    int lane = tid & 31, warp = tid >> 5;
#pragma unroll
    for (int i = 0; i < 33; i++) {
        float x = acc[i];
        for (int off = 16; off; off >>= 1) x += __shfl_down_sync(0xffffffffu, x, off);
        if (lane == 0) part[warp][i] = x;
    }
    __syncthreads();
    if (tid < 33) {
        float s = 0.f;
#pragma unroll
        for (int w = 0; w < 8; w++) s += part[w][tid];
        if (tid < 3) g_Jt[j * 3 + tid] = s;
        else         g_Jsd[j * 30 + (tid - 3)] = s;
    }
}

// ============================================================================
// Kernel 2: build combined W matrix [KP][NPAD]
//   rows 0..9    : shapedirs transposed
//   rows 10..216 : posedirs
//   row  217     : v_template (flattened)
//   rows 218..223, cols >= 20670 : 0
// ============================================================================
__global__ void k_build_W(const float* __restrict__ shapedirs,
                          const float* __restrict__ posedirs,
                          const float* __restrict__ vtmpl) {
    int idx = blockIdx.x * 256 + threadIdx.x;
    int k = idx / NPAD;
    int n = idx % NPAD;
    float val = 0.f;
    if (n < NCOL) {
        if (k < NB)            val = shapedirs[n * NB + k];
        else if (k < NB + NP)  val = posedirs[(k - NB) * NCOL + n];
        else if (k == NB + NP) val = vtmpl[n];
    }
    g_W[idx] = val;
}

// ============================================================================
// Kernel 3: per-batch: rodrigues, pose_feature, AB rows, kinematic chain,
//           A matrices, root, joints output, rot_mats output.
// grid = BATCH, block = 32
// ============================================================================
__global__ void k_batch(const float* __restrict__ pose,     // (B,69)
                        const float* __restrict__ betas,    // (B,10)
                        const float* __restrict__ gorient,  // (B,3)
                        float* __restrict__ out) {
    int b = blockIdx.x;
    int t = threadIdx.x;
    __shared__ float sR[NJ][9];
    __shared__ float sJ[NJ][3];
    __shared__ float sG[NJ][12];

    if (t < NJ) {
        // rodrigues
        float rx, ry, rz;
        if (t == 0) { rx = gorient[b*3+0]; ry = gorient[b*3+1]; rz = gorient[b*3+2]; }
        else { const float* p = pose + b*69 + (t-1)*3; rx = p[0]; ry = p[1]; rz = p[2]; }
        float xa = rx + 1e-8f, ya = ry + 1e-8f, za = rz + 1e-8f;
        float angle = sqrtf(xa*xa + ya*ya + za*za);
        float inv = 1.f / angle;
        float ax = rx*inv, ay = ry*inv, az = rz*inv;
        float s = sinf(angle), c = cosf(angle);
        float K[9] = {0.f,-az,ay, az,0.f,-ax, -ay,ax,0.f};
        float R[9];
#pragma unroll
        for (int r = 0; r < 3; r++)
#pragma unroll
            for (int cc = 0; cc < 3; cc++) {
                float k2 = 0.f;
#pragma unroll
                for (int m = 0; m < 3; m++) k2 += K[r*3+m] * K[m*3+cc];
                R[r*3+cc] = (r==cc ? 1.f : 0.f) + s*K[r*3+cc] + (1.f - c)*k2;
            }
#pragma unroll
        for (int i = 0; i < 9; i++) sR[t][i] = R[i];
        // rot_mats output
#pragma unroll
        for (int i = 0; i < 9; i++) out[OFF_R + (size_t)b*216 + t*9 + i] = R[i];
        // pose_feature -> g_AB
        if (t >= 1) {
#pragma unroll
            for (int i = 0; i < 9; i++) {
                float id = (i==0 || i==4 || i==8) ? 1.f : 0.f;
                g_AB[b*KP + NB + (t-1)*9 + i] = R[i] - id;
            }
        }
        // Jrest
#pragma unroll
        for (int k = 0; k < 3; k++) {
            float jr = g_Jt[t*3 + k];
#pragma unroll
            for (int l = 0; l < NB; l++)
                jr = fmaf(betas[b*NB + l], g_Jsd[t*30 + k*NB + l], jr);
            sJ[t][k] = jr;
        }
    }
    if (t < NB) g_AB[b*KP + t] = betas[b*NB + t];
    if (t == 24) {
        g_AB[b*KP + 217] = 1.f;
#pragma unroll
        for (int i = 218; i < KP; i++) g_AB[b*KP + i] = 0.f;
    }
    __syncthreads();

    if (t == 0) {
        // chain: G0 = (R0 | Jrest0)
#pragma unroll
        for (int r = 0; r < 3; r++) {
            sG[0][r*4+0] = sR[0][r*3+0];
            sG[0][r*4+1] = sR[0][r*3+1];
            sG[0][r*4+2] = sR[0][r*3+2];
            sG[0][r*4+3] = sJ[0][r];
        }
        for (int j = 1; j < NJ; j++) {
            int p = c_parents[j];
            float rel0 = sJ[j][0] - sJ[p][0];
            float rel1 = sJ[j][1] - sJ[p][1];
            float rel2 = sJ[j][2] - sJ[p][2];
#pragma unroll
            for (int r = 0; r < 3; r++) {
                float g0 = sG[p][r*4+0], g1 = sG[p][r*4+1], g2 = sG[p][r*4+2];
#pragma unroll
                for (int cc = 0; cc < 3; cc++)
                    sG[j][r*4+cc] = g0*sR[j][0*3+cc] + g1*sR[j][1*3+cc] + g2*sR[j][2*3+cc];
                sG[j][r*4+3] = g0*rel0 + g1*rel1 + g2*rel2 + sG[p][r*4+3];
            }
        }
        g_root[b*3+0] = sG[0][3];
        g_root[b*3+1] = sG[0][7];
        g_root[b*3+2] = sG[0][11];
    }
    __syncthreads();

    if (t < NJ) {
        // A_j = (G.R | G.t - G.R @ Jrest_j);  joints output
        float j0 = sJ[t][0], j1 = sJ[t][1], j2 = sJ[t][2];
#pragma unroll
        for (int r = 0; r < 3; r++) {
            float g0 = sG[t][r*4+0], g1 = sG[t][r*4+1], g2 = sG[t][r*4+2], gt = sG[t][r*4+3];
            float* A = &g_A[((size_t)b*NJ + t)*12 + r*4];
            A[0] = g0; A[1] = g1; A[2] = g2;
            A[3] = gt - (g0*j0 + g1*j1 + g2*j2);
            out[OFF_J + (size_t)b*72 + t*3 + r] = gt - sG[0][r*4+3];
        }
    }
}

// ============================================================================
// Kernel 4: GEMM  g_vposed[b][n] = g_AB[b][:] . g_W[:][n]
// M=1024, N=20736, K=224.  BM=64, BN=128, BK=16, 256 threads, 8x4 per thread.
// ============================================================================
#define BM 64
#define BN 128
#define BK 16
__global__ void __launch_bounds__(256) k_gemm() {
    __shared__ float As[BK][BM];
    __shared__ float Bs[BK][BN];
    int bm = blockIdx.y * BM;
    int bn = blockIdx.x * BN;
    int tid = threadIdx.x;
    int tx = tid & 31;   // n dim, *4
    int ty = tid >> 5;   // m dim, *8
    float acc[8][4];
#pragma unroll
    for (int i = 0; i < 8; i++)
#pragma unroll
        for (int j = 0; j < 4; j++) acc[i][j] = 0.f;

    int arow = tid >> 2;
    int acol = (tid & 3) * 4;
    int brow = tid >> 4;
    int bcol = (tid & 15) * 8;

    for (int k0 = 0; k0 < KP; k0 += BK) {
        float4 a = *(const float4*)&g_AB[(bm + arow) * KP + k0 + acol];
        As[acol+0][arow] = a.x; As[acol+1][arow] = a.y;
        As[acol+2][arow] = a.z; As[acol+3][arow] = a.w;
        const float* src = &g_W[(size_t)(k0 + brow) * NPAD + bn + bcol];
        float4 b0 = *(const float4*)src;
        float4 b1 = *(const float4*)(src + 4);
        *(float4*)&Bs[brow][bcol]     = b0;
        *(float4*)&Bs[brow][bcol + 4] = b1;
        __syncthreads();
#pragma unroll
        for (int kk = 0; kk < BK; kk++) {
            float ar[8], br[4];
#pragma unroll
            for (int i = 0; i < 8; i++) ar[i] = As[kk][ty*8 + i];
#pragma unroll
            for (int j = 0; j < 4; j++) br[j] = Bs[kk][tx*4 + j];
#pragma unroll
            for (int i = 0; i < 8; i++)
#pragma unroll
                for (int j = 0; j < 4; j++) acc[i][j] = fmaf(ar[i], br[j], acc[i][j]);
        }
        __syncthreads();
    }
#pragma unroll
    for (int i = 0; i < 8; i++) {
        int b = bm + ty*8 + i;
        *(float4*)&g_vposed[(size_t)b * NPAD + bn + tx*4] =
            make_float4(acc[i][0], acc[i][1], acc[i][2], acc[i][3]);
    }
}

// ============================================================================
// Kernel 5: skinning.  block = 8 batches x 128 vertices, 256 threads
// thread: 1 batch x 4 vertices (lane-consecutive for coalescing)
// ============================================================================
#define SK_MB 8
#define SK_VT 128
__global__ void __launch_bounds__(256) k_skin(const float* __restrict__ wgt,
                                              float* __restrict__ out_verts) {
    __shared__ float sW[SK_VT][25];       // padded stride vs bank conflicts
    __shared__ float sA[SK_MB][NJ][12];
    __shared__ float sRoot[SK_MB][3];
    int v0 = blockIdx.x * SK_VT;
    int b0 = blockIdx.y * SK_MB;
    int tid = threadIdx.x;

    for (int i = tid; i < SK_VT * NJ; i += 256) {
        int vv = i / NJ, jj = i % NJ;
        int v = v0 + vv;
        sW[vv][jj] = (v < NV) ? wgt[v * NJ + jj] : 0.f;
    }
    for (int i = tid; i < SK_MB * NJ * 12; i += 256)
        ((float*)sA)[i] = g_A[(size_t)b0 * NJ * 12 + i];
    if (tid < SK_MB * 3)
        sRoot[tid / 3][tid % 3] = g_root[(b0 + tid / 3) * 3 + tid % 3];
    __syncthreads();

    int lane = tid & 31;
    int bi = tid >> 5;
    int b = b0 + bi;
    float T[4][12];
#pragma unroll
    for (int i = 0; i < 4; i++)
#pragma unroll
        for (int r = 0; r < 12; r++) T[i][r] = 0.f;

#pragma unroll
    for (int j = 0; j < NJ; j++) {
        float a[12];
#pragma unroll
        for (int r = 0; r < 12; r++) a[r] = sA[bi][j][r];
#pragma unroll
        for (int i = 0; i < 4; i++) {
            float w = sW[lane + 32*i][j];
#pragma unroll
            for (int r = 0; r < 12; r++) T[i][r] = fmaf(w, a[r], T[i][r]);
        }
    }

    const float* vp = g_vposed + (size_t)b * NPAD;
    float rx = sRoot[bi][0], ry = sRoot[bi][1], rz = sRoot[bi][2];
#pragma unroll
    for (int i = 0; i < 4; i++) {
        int v = v0 + lane + 32*i;
        if (v < NV) {
            float px = vp[v*3+0], py = vp[v*3+1], pz = vp[v*3+2];
            float ox = T[i][0]*px + T[i][1]*py + T[i][2]*pz  + T[i][3]  - rx;
            float oy = T[i][4]*px + T[i][5]*py + T[i][6]*pz  + T[i][7]  - ry;
            float oz = T[i][8]*px + T[i][9]*py + T[i][10]*pz + T[i][11] - rz;
            size_t o = (size_t)b * NCOL + (size_t)v * 3;
            out_verts[o+0] = ox; out_verts[o+1] = oy; out_verts[o+2] = oz;
        }
    }
}

// ============================================================================
// Kernel 6: jfv = (Jh @ verts_out), output s[j]-s[0].  2 batches / block.
// ============================================================================
__global__ void __launch_bounds__(256) k_jfv(const float* __restrict__ verts,
                                             const float* __restrict__ Jh,
                                             float* __restrict__ out_jfv) {
    int b0 = blockIdx.x * 2;
    int tid = threadIdx.x;
    float acc[2][17][3];
#pragma unroll
    for (int bb = 0; bb < 2; bb++)
#pragma unroll
        for (int j = 0; j < 17; j++)
#pragma unroll
            for (int k = 0; k < 3; k++) acc[bb][j][k] = 0.f;

    for (int v = tid; v < NV; v += 256) {
        float jr[17];
#pragma unroll
        for (int j = 0; j < 17; j++) jr[j] = Jh[j * NV + v];
#pragma unroll
        for (int bb = 0; bb < 2; bb++) {
            const float* vb = verts + (size_t)(b0 + bb) * NCOL + (size_t)v * 3;
            float x = vb[0], y = vb[1], z = vb[2];
#pragma unroll
            for (int j = 0; j < 17; j++) {
                acc[bb][j][0] = fmaf(jr[j], x, acc[bb][j][0]);
                acc[bb][j][1] = fmaf(jr[j], y, acc[bb][j][1]);
                acc[bb][j][2] = fmaf(jr[j], z, acc[bb][j][2]);
            }
        }
    }

    __shared__ float red[8][102];
    int lane = tid & 31, warp = tid >> 5;
    float* a = &acc[0][0][0];
#pragma unroll
    for (int i = 0; i < 102; i++) {
        float x = a[i];
        for (int off = 16; off; off >>= 1) x += __shfl_down_sync(0xffffffffu, x, off);
        if (lane == 0) red[warp][i] = x;
    }
    __syncthreads();
    if (tid < 102) {
        float s = 0.f;
#pragma unroll
        for (int w = 0; w < 8; w++) s += red[w][tid];
        red[0][tid] = s;
    }
    __syncthreads();
    if (tid < 102) {
        int bb = tid / 51;
        int jk = tid % 51;
        int k = jk % 3;
        float val = red[0][tid] - red[0][bb * 51 + k];   // s[j] - s[0]
        out_jfv[(size_t)(b0 + bb) * 51 + jk] = val;
    }
}

// ============================================================================
extern "C" void kernel_launch(void* const* d_in, const int* in_sizes, int n_in,
                              void* d_out, int out_size) {
    const float* pose      = (const float*)d_in[0];  // (B,69)
    const float* betas     = (const float*)d_in[1];  // (B,10)
    const float* gorient   = (const float*)d_in[2];  // (B,3)
    const float* vtmpl     = (const float*)d_in[3];  // (V,3)
    const float* shapedirs = (const float*)d_in[4];  // (V,3,10)
    const float* posedirs  = (const float*)d_in[5];  // (207, V*3)
    const float* Jreg      = (const float*)d_in[6];  // (24,V)
    const float* Jh        = (const float*)d_in[7];  // (17,V)
    const float* wgt       = (const float*)d_in[8];  // (V,24)
    float* out = (float*)d_out;

    k_jreg<<<NJ, 256>>>(Jreg, vtmpl, shapedirs);
    k_build_W<<<(KP * NPAD) / 256, 256>>>(shapedirs, posedirs, vtmpl);
    k_batch<<<BATCH, 32>>>(pose, betas, gorient, out);
    k_gemm<<<dim3(NPAD / BN, BATCH / BM), 256>>>();
    k_skin<<<dim3((NV + SK_VT - 1) / SK_VT, BATCH / SK_MB), 256>>>(wgt, out + OFF_VERTS);
    k_jfv<<<BATCH / 2, 256>>>(out + OFF_VERTS, Jh, out + OFF_F);
}

// round 2
// speedup vs baseline: 1.0355x; 1.0355x over previous
#include <cuda_runtime.h>
#include <math.h>

#define BATCH 1024
#define NV    6890
#define NJ    24
#define NB    10
#define NP    207
#define KP    224          // 10 betas + 207 pose_feature + 1 (v_template) + 6 pad
#define NCOL  20670        // V*3
#define NPAD  20736        // padded N (162 * 128)

// ---------------- scratch (device globals; no allocation allowed) ----------------
__device__ float g_W[KP * NPAD];            // combined weight matrix  (18.6 MB)
__device__ float g_vposed[BATCH * NPAD];    // v_posed                 (84.9 MB)
__device__ float g_AB[BATCH * KP];          // per-batch GEMM A rows
__device__ float g_A[BATCH * NJ * 12];      // per-batch skinning transforms (3x4)
__device__ float g_root[BATCH * 3];         // posed joint 0 (root)
__device__ float g_Jt[NJ * 3];              // J_regressor @ v_template
__device__ float g_Jsd[NJ * 3 * NB];        // J_regressor @ shapedirs

__constant__ int c_parents[NJ] = {-1,0,0,0,1,2,3,4,5,6,7,8,9,9,9,12,13,14,16,17,18,19,20,21};

// output section offsets (floats)
#define OFF_VERTS 0
#define OFF_J     (BATCH * NCOL)                 // 21166080
#define OFF_R     (OFF_J + BATCH * NJ * 3)       // +73728
#define OFF_F     (OFF_R + BATCH * NJ * 9)       // +221184

// ---------------- packed f32x2 helpers (dual-FMA per issue slot) ----------------
typedef unsigned long long u64;

__device__ __forceinline__ u64 pack2(float x, float y) {
    u64 r;
    asm("mov.b64 %0, {%1, %2};" : "=l"(r) : "f"(x), "f"(y));
    return r;
}
__device__ __forceinline__ u64 ffma2(u64 a, u64 b, u64 c) {
    u64 d;
    asm("fma.rn.f32x2 %0, %1, %2, %3;" : "=l"(d) : "l"(a), "l"(b), "l"(c));
    return d;
}
__device__ __forceinline__ float2 unpack2(u64 v) {
    float2 f;
    asm("mov.b64 {%0, %1}, %2;" : "=f"(f.x), "=f"(f.y) : "l"(v));
    return f;
}

// ============================================================================
// Kernel 1: factorized joint regressor:  g_Jt[j,k], g_Jsd[j,k,l]
// ============================================================================
__global__ void k_jreg(const float* __restrict__ Jreg,
                       const float* __restrict__ vtmpl,
                       const float* __restrict__ shapedirs) {
    int j = blockIdx.x;
    int tid = threadIdx.x;
    float acc[33];
#pragma unroll
    for (int i = 0; i < 33; i++) acc[i] = 0.f;

    for (int v = tid; v < NV; v += 256) {
        float r = Jreg[j * NV + v];
#pragma unroll
        for (int k = 0; k < 3; k++) {
            acc[k] = fmaf(r, vtmpl[v * 3 + k], acc[k]);
#pragma unroll
            for (int l = 0; l < NB; l++)
                acc[3 + k * NB + l] = fmaf(r, shapedirs[(v * 3 + k) * NB + l], acc[3 + k * NB + l]);
        }
    }
    __shared__ float part[8][33];
    int lane = tid & 31, warp = tid >> 5;
#pragma unroll
    for (int i = 0; i < 33; i++) {
        float x = acc[i];
        for (int off = 16; off; off >>= 1) x += __shfl_down_sync(0xffffffffu, x, off);
        if (lane == 0) part[warp][i] = x;
    }
    __syncthreads();
    if (tid < 33) {
        float s = 0.f;
#pragma unroll
        for (int w = 0; w < 8; w++) s += part[w][tid];
        if (tid < 3) g_Jt[j * 3 + tid] = s;
        else         g_Jsd[j * 30 + (tid - 3)] = s;
    }
}

// ============================================================================
// Kernel 2: build combined W matrix [KP][NPAD]
// ============================================================================
__global__ void k_build_W(const float* __restrict__ shapedirs,
                          const float* __restrict__ posedirs,
                          const float* __restrict__ vtmpl) {
    int idx = blockIdx.x * 256 + threadIdx.x;
    int k = idx / NPAD;
    int n = idx % NPAD;
    float val = 0.f;
    if (n < NCOL) {
        if (k < NB)            val = shapedirs[n * NB + k];
        else if (k < NB + NP)  val = posedirs[(k - NB) * NCOL + n];
        else if (k == NB + NP) val = vtmpl[n];
    }
    g_W[idx] = val;
}

// ============================================================================
// Kernel 3: per-batch rodrigues / chain / A matrices / outputs J & R
// ============================================================================
__global__ void k_batch(const float* __restrict__ pose,
                        const float* __restrict__ betas,
                        const float* __restrict__ gorient,
                        float* __restrict__ out) {
    int b = blockIdx.x;
    int t = threadIdx.x;
    __shared__ float sR[NJ][9];
    __shared__ float sJ[NJ][3];
    __shared__ float sG[NJ][12];

    if (t < NJ) {
        float rx, ry, rz;
        if (t == 0) { rx = gorient[b*3+0]; ry = gorient[b*3+1]; rz = gorient[b*3+2]; }
        else { const float* p = pose + b*69 + (t-1)*3; rx = p[0]; ry = p[1]; rz = p[2]; }
        float xa = rx + 1e-8f, ya = ry + 1e-8f, za = rz + 1e-8f;
        float angle = sqrtf(xa*xa + ya*ya + za*za);
        float inv = 1.f / angle;
        float ax = rx*inv, ay = ry*inv, az = rz*inv;
        float s = sinf(angle), c = cosf(angle);
        float K[9] = {0.f,-az,ay, az,0.f,-ax, -ay,ax,0.f};
        float R[9];
#pragma unroll
        for (int r = 0; r < 3; r++)
#pragma unroll
            for (int cc = 0; cc < 3; cc++) {
                float k2 = 0.f;
#pragma unroll
                for (int m = 0; m < 3; m++) k2 += K[r*3+m] * K[m*3+cc];
                R[r*3+cc] = (r==cc ? 1.f : 0.f) + s*K[r*3+cc] + (1.f - c)*k2;
            }
#pragma unroll
        for (int i = 0; i < 9; i++) sR[t][i] = R[i];
#pragma unroll
        for (int i = 0; i < 9; i++) out[OFF_R + (size_t)b*216 + t*9 + i] = R[i];
        if (t >= 1) {
#pragma unroll
            for (int i = 0; i < 9; i++) {
                float id = (i==0 || i==4 || i==8) ? 1.f : 0.f;
                g_AB[b*KP + NB + (t-1)*9 + i] = R[i] - id;
            }
        }
#pragma unroll
        for (int k = 0; k < 3; k++) {
            float jr = g_Jt[t*3 + k];
#pragma unroll
            for (int l = 0; l < NB; l++)
                jr = fmaf(betas[b*NB + l], g_Jsd[t*30 + k*NB + l], jr);
            sJ[t][k] = jr;
        }
    }
    if (t < NB) g_AB[b*KP + t] = betas[b*NB + t];
    if (t == 24) {
        g_AB[b*KP + 217] = 1.f;
#pragma unroll
        for (int i = 218; i < KP; i++) g_AB[b*KP + i] = 0.f;
    }
    __syncthreads();

    if (t == 0) {
#pragma unroll
        for (int r = 0; r < 3; r++) {
            sG[0][r*4+0] = sR[0][r*3+0];
            sG[0][r*4+1] = sR[0][r*3+1];
            sG[0][r*4+2] = sR[0][r*3+2];
            sG[0][r*4+3] = sJ[0][r];
        }
        for (int j = 1; j < NJ; j++) {
            int p = c_parents[j];
            float rel0 = sJ[j][0] - sJ[p][0];
            float rel1 = sJ[j][1] - sJ[p][1];
            float rel2 = sJ[j][2] - sJ[p][2];
#pragma unroll
            for (int r = 0; r < 3; r++) {
                float g0 = sG[p][r*4+0], g1 = sG[p][r*4+1], g2 = sG[p][r*4+2];
#pragma unroll
                for (int cc = 0; cc < 3; cc++)
                    sG[j][r*4+cc] = g0*sR[j][0*3+cc] + g1*sR[j][1*3+cc] + g2*sR[j][2*3+cc];
                sG[j][r*4+3] = g0*rel0 + g1*rel1 + g2*rel2 + sG[p][r*4+3];
            }
        }
        g_root[b*3+0] = sG[0][3];
        g_root[b*3+1] = sG[0][7];
        g_root[b*3+2] = sG[0][11];
    }
    __syncthreads();

    if (t < NJ) {
        float j0 = sJ[t][0], j1 = sJ[t][1], j2 = sJ[t][2];
#pragma unroll
        for (int r = 0; r < 3; r++) {
            float g0 = sG[t][r*4+0], g1 = sG[t][r*4+1], g2 = sG[t][r*4+2], gt = sG[t][r*4+3];
            float* A = &g_A[((size_t)b*NJ + t)*12 + r*4];
            A[0] = g0; A[1] = g1; A[2] = g2;
            A[3] = gt - (g0*j0 + g1*j1 + g2*j2);
            out[OFF_J + (size_t)b*72 + t*3 + r] = gt - sG[0][r*4+3];
        }
    }
}

// ============================================================================
// Kernel 4: GEMM  g_vposed[b][n] = g_AB[b][:] . g_W[:][n]
// M=1024, N=20736, K=224.  BM=128, BN=128, BK=16, 256 threads, 8x8 per thread
// using packed fma.rn.f32x2 (2 FMA per issue slot).
// ============================================================================
#define BM 128
#define BN 128
#define BK 16
__global__ void __launch_bounds__(256, 2) k_gemm() {
    __shared__ __align__(16) float As[BK][BM];
    __shared__ __align__(16) float Bs[BK][BN];
    int bm = blockIdx.y * BM;
    int bn = blockIdx.x * BN;
    int tid = threadIdx.x;
    int tm = tid >> 4;    // 0..15, m-subtile of 8
    int tn = tid & 15;    // 0..15, n-subtile of 8 (4 f32x2 pairs)

    u64 acc[8][4];
#pragma unroll
    for (int i = 0; i < 8; i++)
#pragma unroll
        for (int j = 0; j < 4; j++) acc[i][j] = 0ull;

    int arow = tid >> 1;          // 0..127
    int acol = (tid & 1) * 8;     // 0 or 8
    int brow = tid >> 4;          // 0..15
    int bcol = (tid & 15) * 8;    // 0..120

    for (int k0 = 0; k0 < KP; k0 += BK) {
        // A tile: 128 x 16, transposed into As[k][m]
        const float* asrc = &g_AB[(bm + arow) * KP + k0 + acol];
        float4 a0 = *(const float4*)asrc;
        float4 a1 = *(const float4*)(asrc + 4);
        As[acol+0][arow] = a0.x; As[acol+1][arow] = a0.y;
        As[acol+2][arow] = a0.z; As[acol+3][arow] = a0.w;
        As[acol+4][arow] = a1.x; As[acol+5][arow] = a1.y;
        As[acol+6][arow] = a1.z; As[acol+7][arow] = a1.w;
        // B tile: 16 x 128
        const float* bsrc = &g_W[(size_t)(k0 + brow) * NPAD + bn + bcol];
        *(float4*)&Bs[brow][bcol]     = *(const float4*)bsrc;
        *(float4*)&Bs[brow][bcol + 4] = *(const float4*)(bsrc + 4);
        __syncthreads();

#pragma unroll
        for (int kk = 0; kk < BK; kk++) {
            float4 av0 = *(const float4*)&As[kk][tm*8];
            float4 av1 = *(const float4*)&As[kk][tm*8 + 4];
            u64 ad[8];
            ad[0] = pack2(av0.x, av0.x); ad[1] = pack2(av0.y, av0.y);
            ad[2] = pack2(av0.z, av0.z); ad[3] = pack2(av0.w, av0.w);
            ad[4] = pack2(av1.x, av1.x); ad[5] = pack2(av1.y, av1.y);
            ad[6] = pack2(av1.z, av1.z); ad[7] = pack2(av1.w, av1.w);
            ulonglong2 bv0 = *(const ulonglong2*)&Bs[kk][tn*8];
            ulonglong2 bv1 = *(const ulonglong2*)&Bs[kk][tn*8 + 4];
            u64 bv[4] = {bv0.x, bv0.y, bv1.x, bv1.y};
#pragma unroll
            for (int i = 0; i < 8; i++)
#pragma unroll
                for (int j = 0; j < 4; j++)
                    acc[i][j] = ffma2(ad[i], bv[j], acc[i][j]);
        }
        __syncthreads();
    }

#pragma unroll
    for (int i = 0; i < 8; i++) {
        int b = bm + tm*8 + i;
        float* dst = &g_vposed[(size_t)b * NPAD + bn + tn*8];
        float2 p0 = unpack2(acc[i][0]);
        float2 p1 = unpack2(acc[i][1]);
        float2 p2 = unpack2(acc[i][2]);
        float2 p3 = unpack2(acc[i][3]);
        *(float4*)dst       = make_float4(p0.x, p0.y, p1.x, p1.y);
        *(float4*)(dst + 4) = make_float4(p2.x, p2.y, p3.x, p3.y);
    }
}

// ============================================================================
// Kernel 5: skinning, packed f32x2 accumulation.
// block = 8 batches x 128 vertices, 256 threads; thread = 1 batch x 4 verts
// ============================================================================
#define SK_MB 8
#define SK_VT 128
__global__ void __launch_bounds__(256) k_skin(const float* __restrict__ wgt,
                                              float* __restrict__ out_verts) {
    __shared__ __align__(16) float sW[SK_VT][25];
    __shared__ __align__(16) float sA[SK_MB][NJ][12];
    __shared__ float sRoot[SK_MB][3];
    int v0 = blockIdx.x * SK_VT;
    int b0 = blockIdx.y * SK_MB;
    int tid = threadIdx.x;

    for (int i = tid; i < SK_VT * NJ; i += 256) {
        int vv = i / NJ, jj = i % NJ;
        int v = v0 + vv;
        sW[vv][jj] = (v < NV) ? wgt[v * NJ + jj] : 0.f;
    }
    for (int i = tid; i < SK_MB * NJ * 12; i += 256)
        ((float*)sA)[i] = g_A[(size_t)b0 * NJ * 12 + i];
    if (tid < SK_MB * 3)
        sRoot[tid / 3][tid % 3] = g_root[(b0 + tid / 3) * 3 + tid % 3];
    __syncthreads();

    int lane = tid & 31;
    int bi = tid >> 5;
    int b = b0 + bi;

    u64 T2[4][6];
#pragma unroll
    for (int i = 0; i < 4; i++)
#pragma unroll
        for (int r = 0; r < 6; r++) T2[i][r] = 0ull;

#pragma unroll
    for (int j = 0; j < NJ; j++) {
        const u64* a2 = (const u64*)&sA[bi][j][0];
        u64 av[6];
#pragma unroll
        for (int r = 0; r < 6; r++) av[r] = a2[r];
#pragma unroll
        for (int i = 0; i < 4; i++) {
            float w = sW[lane + 32*i][j];
            u64 w2 = pack2(w, w);
#pragma unroll
            for (int r = 0; r < 6; r++) T2[i][r] = ffma2(w2, av[r], T2[i][r]);
        }
    }

    const float* vp = g_vposed + (size_t)b * NPAD;
    float rx = sRoot[bi][0], ry = sRoot[bi][1], rz = sRoot[bi][2];
#pragma unroll
    for (int i = 0; i < 4; i++) {
        int v = v0 + lane + 32*i;
        if (v < NV) {
            float T[12];
#pragma unroll
            for (int r = 0; r < 6; r++) {
                float2 f = unpack2(T2[i][r]);
                T[2*r] = f.x; T[2*r+1] = f.y;
            }
            float px = vp[v*3+0], py = vp[v*3+1], pz = vp[v*3+2];
            float ox = T[0]*px + T[1]*py + T[2]*pz  + T[3]  - rx;
            float oy = T[4]*px + T[5]*py + T[6]*pz  + T[7]  - ry;
            float oz = T[8]*px + T[9]*py + T[10]*pz + T[11] - rz;
            size_t o = (size_t)b * NCOL + (size_t)v * 3;
            out_verts[o+0] = ox; out_verts[o+1] = oy; out_verts[o+2] = oz;
        }
    }
}

// ============================================================================
// Kernel 6: jfv = (Jh @ verts_out), output s[j]-s[0].  2 batches / block.
// ============================================================================
__global__ void __launch_bounds__(256) k_jfv(const float* __restrict__ verts,
                                             const float* __restrict__ Jh,
                                             float* __restrict__ out_jfv) {
    int b0 = blockIdx.x * 2;
    int tid = threadIdx.x;
    float acc[2][17][3];
#pragma unroll
    for (int bb = 0; bb < 2; bb++)
#pragma unroll
        for (int j = 0; j < 17; j++)
#pragma unroll
            for (int k = 0; k < 3; k++) acc[bb][j][k] = 0.f;

    for (int v = tid; v < NV; v += 256) {
        float jr[17];
#pragma unroll
        for (int j = 0; j < 17; j++) jr[j] = Jh[j * NV + v];
#pragma unroll
        for (int bb = 0; bb < 2; bb++) {
            const float* vb = verts + (size_t)(b0 + bb) * NCOL + (size_t)v * 3;
            float x = vb[0], y = vb[1], z = vb[2];
#pragma unroll
            for (int j = 0; j < 17; j++) {
                acc[bb][j][0] = fmaf(jr[j], x, acc[bb][j][0]);
                acc[bb][j][1] = fmaf(jr[j], y, acc[bb][j][1]);
                acc[bb][j][2] = fmaf(jr[j], z, acc[bb][j][2]);
            }
        }
    }

    __shared__ float red[8][102];
    int lane = tid & 31, warp = tid >> 5;
    float* a = &acc[0][0][0];
#pragma unroll
    for (int i = 0; i < 102; i++) {
        float x = a[i];
        for (int off = 16; off; off >>= 1) x += __shfl_down_sync(0xffffffffu, x, off);
        if (lane == 0) red[warp][i] = x;
    }
    __syncthreads();
    if (tid < 102) {
        float s = 0.f;
#pragma unroll
        for (int w = 0; w < 8; w++) s += red[w][tid];
        red[0][tid] = s;
    }
    __syncthreads();
    if (tid < 102) {
        int bb = tid / 51;
        int jk = tid % 51;
        int k = jk % 3;
        float val = red[0][tid] - red[0][bb * 51 + k];   // s[j] - s[0]
        out_jfv[(size_t)(b0 + bb) * 51 + jk] = val;
    }
}

// ============================================================================
extern "C" void kernel_launch(void* const* d_in, const int* in_sizes, int n_in,
                              void* d_out, int out_size) {
    const float* pose      = (const float*)d_in[0];  // (B,69)
    const float* betas     = (const float*)d_in[1];  // (B,10)
    const float* gorient   = (const float*)d_in[2];  // (B,3)
    const float* vtmpl     = (const float*)d_in[3];  // (V,3)
    const float* shapedirs = (const float*)d_in[4];  // (V,3,10)
    const float* posedirs  = (const float*)d_in[5];  // (207, V*3)
    const float* Jreg      = (const float*)d_in[6];  // (24,V)
    const float* Jh        = (const float*)d_in[7];  // (17,V)
    const float* wgt       = (const float*)d_in[8];  // (V,24)
    float* out = (float*)d_out;

    k_jreg<<<NJ, 256>>>(Jreg, vtmpl, shapedirs);
    k_build_W<<<(KP * NPAD) / 256, 256>>>(shapedirs, posedirs, vtmpl);
    k_batch<<<BATCH, 32>>>(pose, betas, gorient, out);
    k_gemm<<<dim3(NPAD / BN, BATCH / BM), 256>>>();
    k_skin<<<dim3((NV + SK_VT - 1) / SK_VT, BATCH / SK_MB), 256>>>(wgt, out + OFF_VERTS);
    k_jfv<<<BATCH / 2, 256>>>(out + OFF_VERTS, Jh, out + OFF_F);
}

// round 3
// speedup vs baseline: 1.4102x; 1.3618x over previous
#include <cuda_runtime.h>
#include <math.h>
#include <stdint.h>

#define BATCH 1024
#define NV    6890
#define NJ    24
#define NB    10
#define NP    207
#define KP    224          // 10 betas + 207 pose_feature + 7 pad (v_template handled in skin)
#define KA    28           // KP / 8 k-atoms
#define NCOL  20670        // V*3
#define NPAD  20736        // padded N (162 * 128)
#define NBLK  162          // NPAD / 128
#define MBLK  8            // BATCH / 128

// ---------------- scratch (device globals; no allocation allowed) ----------------
__device__ float g_Bfrag[NBLK * KA * 16 * 32 * 2];   // tf32 B fragments (18.6 MB)
__device__ float g_Afrag[MBLK * KA * 8 * 32 * 4];    // tf32 A fragments (917 KB)
__device__ float g_vposed[BATCH * NPAD];             // v_posed minus template (84.9 MB)
__device__ float g_AB[BATCH * KP];                   // per-batch GEMM A rows
__device__ float g_A[BATCH * NJ * 12];               // per-batch skinning transforms (3x4)
__device__ float g_root[BATCH * 3];                  // posed joint 0 (root)
__device__ float g_Jt[NJ * 3];                       // J_regressor @ v_template
__device__ float g_Jsd[NJ * 3 * NB];                 // J_regressor @ shapedirs

__constant__ int c_parents[NJ] = {-1,0,0,0,1,2,3,4,5,6,7,8,9,9,9,12,13,14,16,17,18,19,20,21};

// output section offsets (floats)
#define OFF_VERTS 0
#define OFF_J     (BATCH * NCOL)
#define OFF_R     (OFF_J + BATCH * NJ * 3)
#define OFF_F     (OFF_R + BATCH * NJ * 9)

// ---------------- helpers ----------------
__device__ __forceinline__ uint32_t tf32_bits(float x) {
    uint32_t u;
    asm("cvt.rna.tf32.f32 %0, %1;" : "=r"(u) : "f"(x));
    return u;
}
__device__ __forceinline__ void mma_tf32(float4& d, uint4 a, uint2 b) {
    asm volatile(
        "mma.sync.aligned.m16n8k8.row.col.f32.tf32.tf32.f32 "
        "{%0,%1,%2,%3}, {%4,%5,%6,%7}, {%8,%9}, {%0,%1,%2,%3};"
        : "+f"(d.x), "+f"(d.y), "+f"(d.z), "+f"(d.w)
        : "r"(a.x), "r"(a.y), "r"(a.z), "r"(a.w), "r"(b.x), "r"(b.y));
}

// ============================================================================
// Kernel 1: factorized joint regressor:  g_Jt[j,k], g_Jsd[j,k,l]
// ============================================================================
__global__ void k_jreg(const float* __restrict__ Jreg,
                       const float* __restrict__ vtmpl,
                       const float* __restrict__ shapedirs) {
    int j = blockIdx.x;
    int tid = threadIdx.x;
    float acc[33];
#pragma unroll
    for (int i = 0; i < 33; i++) acc[i] = 0.f;

    for (int v = tid; v < NV; v += 256) {
        float r = Jreg[j * NV + v];
#pragma unroll
        for (int k = 0; k < 3; k++) {
            acc[k] = fmaf(r, vtmpl[v * 3 + k], acc[k]);
#pragma unroll
            for (int l = 0; l < NB; l++)
                acc[3 + k * NB + l] = fmaf(r, shapedirs[(v * 3 + k) * NB + l], acc[3 + k * NB + l]);
        }
    }
    __shared__ float part[8][33];
    int lane = tid & 31, warp = tid >> 5;
#pragma unroll
    for (int i = 0; i < 33; i++) {
        float x = acc[i];
        for (int off = 16; off; off >>= 1) x += __shfl_down_sync(0xffffffffu, x, off);
        if (lane == 0) part[warp][i] = x;
    }
    __syncthreads();
    if (tid < 33) {
        float s = 0.f;
#pragma unroll
        for (int w = 0; w < 8; w++) s += part[w][tid];
        if (tid < 3) g_Jt[j * 3 + tid] = s;
        else         g_Jsd[j * 30 + (tid - 3)] = s;
    }
}

// ============================================================================
// Kernel 2: build tf32 B fragments.  block = (n_blk, ka); 256 threads.
//   W[k][n]: k<10 -> shapedirs[n*10+k]; 10<=k<217 -> posedirs[(k-10)*NCOL+n]; else 0
//   fragment (m16n8k8 row.col, B col-major 8x8):
//     b0 = W[ka*8 + tig][n0 + g],  b1 = W[ka*8 + tig + 4][n0 + g]
// ============================================================================
__global__ void __launch_bounds__(256) k_build_Bfrag(const float* __restrict__ shapedirs,
                                                     const float* __restrict__ posedirs) {
    __shared__ float sW8[8][128];
    int n_blk = blockIdx.x;
    int ka = blockIdx.y;
    int tid = threadIdx.x;

#pragma unroll
    for (int r = 0; r < 4; r++) {
        int e = tid + r * 256;          // 0..1023
        int kk = e >> 7;                // 0..7
        int nn = e & 127;
        int k = ka * 8 + kk;
        int n = n_blk * 128 + nn;
        float val = 0.f;
        if (n < NCOL) {
            if (k < NB)            val = shapedirs[n * NB + k];
            else if (k < NB + NP)  val = posedirs[(k - NB) * NCOL + n];
        }
        sW8[kk][nn] = val;
    }
    __syncthreads();

    float2* gB = (float2*)g_Bfrag;
#pragma unroll
    for (int r = 0; r < 2; r++) {
        int e = tid + r * 256;          // 0..511
        int n_sub = e >> 5;             // 0..15
        int t = e & 31;
        int g = t >> 2, tig = t & 3;
        float b0 = sW8[tig][n_sub * 8 + g];
        float b1 = sW8[tig + 4][n_sub * 8 + g];
        float2 v;
        v.x = __uint_as_float(tf32_bits(b0));
        v.y = __uint_as_float(tf32_bits(b1));
        gB[((size_t)(n_blk * KA + ka) * 16 + n_sub) * 32 + t] = v;
    }
}

// ============================================================================
// Kernel 3: per-batch rodrigues / chain / A matrices / outputs J & R
// ============================================================================
__global__ void k_batch(const float* __restrict__ pose,
                        const float* __restrict__ betas,
                        const float* __restrict__ gorient,
                        float* __restrict__ out) {
    int b = blockIdx.x;
    int t = threadIdx.x;
    __shared__ float sR[NJ][9];
    __shared__ float sJ[NJ][3];
    __shared__ float sG[NJ][12];

    if (t < NJ) {
        float rx, ry, rz;
        if (t == 0) { rx = gorient[b*3+0]; ry = gorient[b*3+1]; rz = gorient[b*3+2]; }
        else { const float* p = pose + b*69 + (t-1)*3; rx = p[0]; ry = p[1]; rz = p[2]; }
        float xa = rx + 1e-8f, ya = ry + 1e-8f, za = rz + 1e-8f;
        float angle = sqrtf(xa*xa + ya*ya + za*za);
        float inv = 1.f / angle;
        float ax = rx*inv, ay = ry*inv, az = rz*inv;
        float s = sinf(angle), c = cosf(angle);
        float K[9] = {0.f,-az,ay, az,0.f,-ax, -ay,ax,0.f};
        float R[9];
#pragma unroll
        for (int r = 0; r < 3; r++)
#pragma unroll
            for (int cc = 0; cc < 3; cc++) {
                float k2 = 0.f;
#pragma unroll
                for (int m = 0; m < 3; m++) k2 += K[r*3+m] * K[m*3+cc];
                R[r*3+cc] = (r==cc ? 1.f : 0.f) + s*K[r*3+cc] + (1.f - c)*k2;
            }
#pragma unroll
        for (int i = 0; i < 9; i++) sR[t][i] = R[i];
#pragma unroll
        for (int i = 0; i < 9; i++) out[OFF_R + (size_t)b*216 + t*9 + i] = R[i];
        if (t >= 1) {
#pragma unroll
            for (int i = 0; i < 9; i++) {
                float id = (i==0 || i==4 || i==8) ? 1.f : 0.f;
                g_AB[b*KP + NB + (t-1)*9 + i] = R[i] - id;
            }
        }
#pragma unroll
        for (int k = 0; k < 3; k++) {
            float jr = g_Jt[t*3 + k];
#pragma unroll
            for (int l = 0; l < NB; l++)
                jr = fmaf(betas[b*NB + l], g_Jsd[t*30 + k*NB + l], jr);
            sJ[t][k] = jr;
        }
    }
    if (t < NB) g_AB[b*KP + t] = betas[b*NB + t];
    if (t == 24) {
#pragma unroll
        for (int i = NB + NP; i < KP; i++) g_AB[b*KP + i] = 0.f;   // pad rows zero
    }
    __syncthreads();

    if (t == 0) {
#pragma unroll
        for (int r = 0; r < 3; r++) {
            sG[0][r*4+0] = sR[0][r*3+0];
            sG[0][r*4+1] = sR[0][r*3+1];
            sG[0][r*4+2] = sR[0][r*3+2];
            sG[0][r*4+3] = sJ[0][r];
        }
        for (int j = 1; j < NJ; j++) {
            int p = c_parents[j];
            float rel0 = sJ[j][0] - sJ[p][0];
            float rel1 = sJ[j][1] - sJ[p][1];
            float rel2 = sJ[j][2] - sJ[p][2];
#pragma unroll
            for (int r = 0; r < 3; r++) {
                float g0 = sG[p][r*4+0], g1 = sG[p][r*4+1], g2 = sG[p][r*4+2];
#pragma unroll
                for (int cc = 0; cc < 3; cc++)
                    sG[j][r*4+cc] = g0*sR[j][0*3+cc] + g1*sR[j][1*3+cc] + g2*sR[j][2*3+cc];
                sG[j][r*4+3] = g0*rel0 + g1*rel1 + g2*rel2 + sG[p][r*4+3];
            }
        }
        g_root[b*3+0] = sG[0][3];
        g_root[b*3+1] = sG[0][7];
        g_root[b*3+2] = sG[0][11];
    }
    __syncthreads();

    if (t < NJ) {
        float j0 = sJ[t][0], j1 = sJ[t][1], j2 = sJ[t][2];
#pragma unroll
        for (int r = 0; r < 3; r++) {
            float g0 = sG[t][r*4+0], g1 = sG[t][r*4+1], g2 = sG[t][r*4+2], gt = sG[t][r*4+3];
            float* A = &g_A[((size_t)b*NJ + t)*12 + r*4];
            A[0] = g0; A[1] = g1; A[2] = g2;
            A[3] = gt - (g0*j0 + g1*j1 + g2*j2);
            out[OFF_J + (size_t)b*72 + t*3 + r] = gt - sG[0][r*4+3];
        }
    }
}

// ============================================================================
// Kernel 3b: pack A fragments (tf32).  57344 threads.
//   a0=A[g][tig], a1=A[g+8][tig], a2=A[g][tig+4], a3=A[g+8][tig+4]
// ============================================================================
__global__ void __launch_bounds__(256) k_packA() {
    int idx = blockIdx.x * 256 + threadIdx.x;     // 0 .. 8*28*8*32-1
    int t = idx & 31;
    int m_sub = (idx >> 5) & 7;
    int rest = idx >> 8;                          // 0..223
    int ka = rest % KA;
    int m_blk = rest / KA;
    int g = t >> 2, tig = t & 3;
    int row0 = m_blk * 128 + m_sub * 16 + g;
    int k0 = ka * 8 + tig;
    uint4 a;
    a.x = tf32_bits(g_AB[row0 * KP + k0]);
    a.y = tf32_bits(g_AB[(row0 + 8) * KP + k0]);
    a.z = tf32_bits(g_AB[row0 * KP + k0 + 4]);
    a.w = tf32_bits(g_AB[(row0 + 8) * KP + k0 + 4]);
    ((uint4*)g_Afrag)[((size_t)(m_blk * KA + ka) * 8 + m_sub) * 32 + t] = a;
}

// ============================================================================
// Kernel 4: tf32 tensor-core GEMM.  Block 128x128, 8 warps (4m x 2n),
// warp tile 32x64 (2 m-atoms x 8 n-atoms), K loop over 28 k-atoms.
// Fragments pre-packed -> smem copies are linear, LDS conflict-free.
// ============================================================================
__global__ void __launch_bounds__(256, 2) k_gemm() {
    __shared__ uint4 sA[2][8][32];     // [buf][m_sub][t]
    __shared__ uint2 sB[2][16][32];    // [buf][n_sub][t]
    int n_blk = blockIdx.x;
    int m_blk = blockIdx.y;
    int tid = threadIdx.x;
    int lane = tid & 31;
    int wid = tid >> 5;
    int wm = wid >> 1;                 // 0..3
    int wn = wid & 1;                  // 0..1

    const uint4* gA = (const uint4*)g_Afrag + (size_t)m_blk * KA * 256;
    const uint2* gB = (const uint2*)g_Bfrag + (size_t)n_blk * KA * 512;

    float4 acc[2][8];
#pragma unroll
    for (int i = 0; i < 2; i++)
#pragma unroll
        for (int j = 0; j < 8; j++) acc[i][j] = make_float4(0.f, 0.f, 0.f, 0.f);

    // prefetch ka=0
    uint4 pa = gA[tid];
    uint2 pb0 = gB[tid];
    uint2 pb1 = gB[tid + 256];

    int a_ms = tid >> 5;               // m_sub for the A copy slot
    int b_ns0 = tid >> 5;              // n_sub for first B slot (0..7)
    int b_ns1 = 8 + (tid >> 5);        // n_sub for second B slot (8..15)

    for (int ka = 0; ka < KA; ka++) {
        int buf = ka & 1;
        sA[buf][a_ms][lane] = pa;
        sB[buf][b_ns0][lane] = pb0;
        sB[buf][b_ns1][lane] = pb1;
        __syncthreads();
        if (ka + 1 < KA) {
            pa  = gA[(ka + 1) * 256 + tid];
            pb0 = gB[(ka + 1) * 512 + tid];
            pb1 = gB[(ka + 1) * 512 + tid + 256];
        }
        uint4 af[2];
        af[0] = sA[buf][wm * 2 + 0][lane];
        af[1] = sA[buf][wm * 2 + 1][lane];
        uint2 bf[8];
#pragma unroll
        for (int j = 0; j < 8; j++) bf[j] = sB[buf][wn * 8 + j][lane];
#pragma unroll
        for (int i = 0; i < 2; i++)
#pragma unroll
            for (int j = 0; j < 8; j++)
                mma_tf32(acc[i][j], af[i], bf[j]);
        // no trailing sync needed: double-buffered, next store targets other buffer
    }

    // epilogue
    int g = lane >> 2, tig = lane & 3;
#pragma unroll
    for (int i = 0; i < 2; i++) {
        int r0 = m_blk * 128 + (wm * 2 + i) * 16 + g;
#pragma unroll
        for (int j = 0; j < 8; j++) {
            int c = n_blk * 128 + (wn * 8 + j) * 8 + tig * 2;
            float2 lo = make_float2(acc[i][j].x, acc[i][j].y);
            float2 hi = make_float2(acc[i][j].z, acc[i][j].w);
            *(float2*)&g_vposed[(size_t)r0 * NPAD + c] = lo;
            *(float2*)&g_vposed[(size_t)(r0 + 8) * NPAD + c] = hi;
        }
    }
}

// ============================================================================
// Kernel 5: skinning (+ v_template add, fp32 exact).
// block = 8 batches x 128 vertices, 256 threads; thread = 1 batch x 4 verts
// ============================================================================
#define SK_MB 8
#define SK_VT 128
typedef unsigned long long u64;
__device__ __forceinline__ u64 pack2(float x, float y) {
    u64 r; asm("mov.b64 %0, {%1, %2};" : "=l"(r) : "f"(x), "f"(y)); return r;
}
__device__ __forceinline__ u64 ffma2(u64 a, u64 b, u64 c) {
    u64 d; asm("fma.rn.f32x2 %0, %1, %2, %3;" : "=l"(d) : "l"(a), "l"(b), "l"(c)); return d;
}
__device__ __forceinline__ float2 unpack2(u64 v) {
    float2 f; asm("mov.b64 {%0, %1}, %2;" : "=f"(f.x), "=f"(f.y) : "l"(v)); return f;
}

__global__ void __launch_bounds__(256) k_skin(const float* __restrict__ wgt,
                                              const float* __restrict__ vtmpl,
                                              float* __restrict__ out_verts) {
    __shared__ __align__(16) float sW[SK_VT][25];
    __shared__ __align__(16) float sA[SK_MB][NJ][12];
    __shared__ float sRoot[SK_MB][3];
    __shared__ float sVT[SK_VT * 3];
    int v0 = blockIdx.x * SK_VT;
    int b0 = blockIdx.y * SK_MB;
    int tid = threadIdx.x;

    for (int i = tid; i < SK_VT * NJ; i += 256) {
        int vv = i / NJ, jj = i % NJ;
        int v = v0 + vv;
        sW[vv][jj] = (v < NV) ? wgt[v * NJ + jj] : 0.f;
    }
    for (int i = tid; i < SK_MB * NJ * 12; i += 256)
        ((float*)sA)[i] = g_A[(size_t)b0 * NJ * 12 + i];
    for (int i = tid; i < SK_VT * 3; i += 256) {
        int idx = v0 * 3 + i;
        sVT[i] = (idx < NCOL) ? vtmpl[idx] : 0.f;
    }
    if (tid < SK_MB * 3)
        sRoot[tid / 3][tid % 3] = g_root[(b0 + tid / 3) * 3 + tid % 3];
    __syncthreads();

    int lane = tid & 31;
    int bi = tid >> 5;
    int b = b0 + bi;

    u64 T2[4][6];
#pragma unroll
    for (int i = 0; i < 4; i++)
#pragma unroll
        for (int r = 0; r < 6; r++) T2[i][r] = 0ull;

#pragma unroll
    for (int j = 0; j < NJ; j++) {
        const u64* a2 = (const u64*)&sA[bi][j][0];
        u64 av[6];
#pragma unroll
        for (int r = 0; r < 6; r++) av[r] = a2[r];
#pragma unroll
        for (int i = 0; i < 4; i++) {
            float w = sW[lane + 32*i][j];
            u64 w2 = pack2(w, w);
#pragma unroll
            for (int r = 0; r < 6; r++) T2[i][r] = ffma2(w2, av[r], T2[i][r]);
        }
    }

    const float* vp = g_vposed + (size_t)b * NPAD;
    float rx = sRoot[bi][0], ry = sRoot[bi][1], rz = sRoot[bi][2];
#pragma unroll
    for (int i = 0; i < 4; i++) {
        int v = v0 + lane + 32*i;
        if (v < NV) {
            float T[12];
#pragma unroll
            for (int r = 0; r < 6; r++) {
                float2 f = unpack2(T2[i][r]);
                T[2*r] = f.x; T[2*r+1] = f.y;
            }
            int vv = lane + 32*i;
            float px = vp[v*3+0] + sVT[vv*3+0];
            float py = vp[v*3+1] + sVT[vv*3+1];
            float pz = vp[v*3+2] + sVT[vv*3+2];
            float ox = T[0]*px + T[1]*py + T[2]*pz  + T[3]  - rx;
            float oy = T[4]*px + T[5]*py + T[6]*pz  + T[7]  - ry;
            float oz = T[8]*px + T[9]*py + T[10]*pz + T[11] - rz;
            size_t o = (size_t)b * NCOL + (size_t)v * 3;
            out_verts[o+0] = ox; out_verts[o+1] = oy; out_verts[o+2] = oz;
        }
    }
}

// ============================================================================
// Kernel 6: jfv = (Jh @ verts_out), output s[j]-s[0].  2 batches / block.
// ============================================================================
__global__ void __launch_bounds__(256) k_jfv(const float* __restrict__ verts,
                                             const float* __restrict__ Jh,
                                             float* __restrict__ out_jfv) {
    int b0 = blockIdx.x * 2;
    int tid = threadIdx.x;
    float acc[2][17][3];
#pragma unroll
    for (int bb = 0; bb < 2; bb++)
#pragma unroll
        for (int j = 0; j < 17; j++)
#pragma unroll
            for (int k = 0; k < 3; k++) acc[bb][j][k] = 0.f;

    for (int v = tid; v < NV; v += 256) {
        float jr[17];
#pragma unroll
        for (int j = 0; j < 17; j++) jr[j] = Jh[j * NV + v];
#pragma unroll
        for (int bb = 0; bb < 2; bb++) {
            const float* vb = verts + (size_t)(b0 + bb) * NCOL + (size_t)v * 3;
            float x = vb[0], y = vb[1], z = vb[2];
#pragma unroll
            for (int j = 0; j < 17; j++) {
                acc[bb][j][0] = fmaf(jr[j], x, acc[bb][j][0]);
                acc[bb][j][1] = fmaf(jr[j], y, acc[bb][j][1]);
                acc[bb][j][2] = fmaf(jr[j], z, acc[bb][j][2]);
            }
        }
    }

    __shared__ float red[8][102];
    int lane = tid & 31, warp = tid >> 5;
    float* a = &acc[0][0][0];
#pragma unroll
    for (int i = 0; i < 102; i++) {
        float x = a[i];
        for (int off = 16; off; off >>= 1) x += __shfl_down_sync(0xffffffffu, x, off);
        if (lane == 0) red[warp][i] = x;
    }
    __syncthreads();
    if (tid < 102) {
        float s = 0.f;
#pragma unroll
        for (int w = 0; w < 8; w++) s += red[w][tid];
        red[0][tid] = s;
    }
    __syncthreads();
    if (tid < 102) {
        int bb = tid / 51;
        int jk = tid % 51;
        int k = jk % 3;
        float val = red[0][tid] - red[0][bb * 51 + k];   // s[j] - s[0]
        out_jfv[(size_t)(b0 + bb) * 51 + jk] = val;
    }
}

// ============================================================================
extern "C" void kernel_launch(void* const* d_in, const int* in_sizes, int n_in,
                              void* d_out, int out_size) {
    const float* pose      = (const float*)d_in[0];  // (B,69)
    const float* betas     = (const float*)d_in[1];  // (B,10)
    const float* gorient   = (const float*)d_in[2];  // (B,3)
    const float* vtmpl     = (const float*)d_in[3];  // (V,3)
    const float* shapedirs = (const float*)d_in[4];  // (V,3,10)
    const float* posedirs  = (const float*)d_in[5];  // (207, V*3)
    const float* Jreg      = (const float*)d_in[6];  // (24,V)
    const float* Jh        = (const float*)d_in[7];  // (17,V)
    const float* wgt       = (const float*)d_in[8];  // (V,24)
    float* out = (float*)d_out;

    k_jreg<<<NJ, 256>>>(Jreg, vtmpl, shapedirs);
    k_build_Bfrag<<<dim3(NBLK, KA), 256>>>(shapedirs, posedirs);
    k_batch<<<BATCH, 32>>>(pose, betas, gorient, out);
    k_packA<<<(MBLK * KA * 8 * 32) / 256, 256>>>();
    k_gemm<<<dim3(NBLK, MBLK), 256>>>();
    k_skin<<<dim3((NV + SK_VT - 1) / SK_VT, BATCH / SK_MB), 256>>>(wgt, vtmpl, out + OFF_VERTS);
    k_jfv<<<BATCH / 2, 256>>>(out + OFF_VERTS, Jh, out + OFF_F);
}